// round 1
// baseline (speedup 1.0000x reference)
#include <cuda_runtime.h>
#include <math.h>

#define T_DIM 1024
#define NP    32
#define DP    8
#define NT    16
#define DT    16
#define O_DIM 256   // NT*DT
#define KTAP  3

__global__ __launch_bounds__(256, 4)
void caps_kernel(const float* __restrict__ x,
                 const float* __restrict__ K,
                 const float* __restrict__ bias,
                 const float* __restrict__ Bw,
                 float* __restrict__ out)
{
    const int bt  = blockIdx.x;            // b*T + t
    const int t   = bt & (T_DIM - 1);
    const int tid = threadIdx.x;           // output channel o = n*16+d

    __shared__ float xw[KTAP][NP][DP];     // conv input window, 3 KB
    __shared__ float su[NP][O_DIM];        // y/U tile: su[p][n*16+d], 32 KB
    __shared__ float sv[O_DIM];            // v[n][d] = sum_p U[n,p,d]
    __shared__ float ssm[NT][NP];          // scores then softmax
    __shared__ float sw[NT][NP];           // C + B_weight

    // ---- load x window (rows t-1, t, t+1; zero-pad at batch-sequence edges)
    const float* xbase = x + (size_t)bt * (NP * DP);
    #pragma unroll
    for (int r = 0; r < KTAP; r++) {
        int tt = t + r - 1;
        float v = 0.f;
        if (tt >= 0 && tt < T_DIM) v = xbase[(r - 1) * (NP * DP) + tid];
        (&xw[r][0][0])[tid] = v;
    }

    // ---- conv weights for this output channel: K[(kt*8+d)*256 + o] (coalesced)
    float kr[24];
    #pragma unroll
    for (int i = 0; i < 24; i++) kr[i] = K[i * O_DIM + tid];
    const float bo = bias[tid];
    __syncthreads();

    // ---- conv + relu: y[p][o] = relu(bias + sum_{kt,d} xw[kt][p][d]*kr[kt*8+d])
    #pragma unroll 4
    for (int p = 0; p < NP; p++) {
        float acc = bo;
        #pragma unroll
        for (int r = 0; r < KTAP; r++) {
            float4 a = *(const float4*)&xw[r][p][0];
            float4 b = *(const float4*)&xw[r][p][4];
            acc = fmaf(a.x, kr[r * 8 + 0], acc);
            acc = fmaf(a.y, kr[r * 8 + 1], acc);
            acc = fmaf(a.z, kr[r * 8 + 2], acc);
            acc = fmaf(a.w, kr[r * 8 + 3], acc);
            acc = fmaf(b.x, kr[r * 8 + 4], acc);
            acc = fmaf(b.y, kr[r * 8 + 5], acc);
            acc = fmaf(b.z, kr[r * 8 + 6], acc);
            acc = fmaf(b.w, kr[r * 8 + 7], acc);
        }
        su[p][tid] = fmaxf(acc, 0.f);
    }
    __syncthreads();

    // ---- v[n][d] = sum_p U[n,p,d]  (thread o sums column o of su)
    {
        float v = 0.f;
        #pragma unroll
        for (int p = 0; p < NP; p++) v += su[p][tid];
        sv[tid] = v;
    }
    __syncthreads();

    // ---- s[n][q] = dot(v[n,:], U[n,q,:]) / sqrt(8)   (512 values, 2/thread)
    #pragma unroll
    for (int i = tid; i < NT * NP; i += 256) {
        const int n = i >> 5;
        const int q = i & 31;
        float acc = 0.f;
        #pragma unroll
        for (int d = 0; d < DT; d++)
            acc = fmaf(sv[n * 16 + d], su[q][n * 16 + d], acc);
        ssm[n][q] = acc * 0.35355339059327373f;   // 1/sqrt(8)
    }
    __syncthreads();

    // ---- softmax over q per row n (16 rows; one thread per row, recompute exp)
    if (tid < NT) {
        float m = -1e30f;
        #pragma unroll
        for (int q = 0; q < NP; q++) m = fmaxf(m, ssm[tid][q]);
        float sum = 0.f;
        #pragma unroll
        for (int q = 0; q < NP; q++) sum += __expf(ssm[tid][q] - m);
        float inv = 1.f / sum;
        #pragma unroll
        for (int q = 0; q < NP; q++)
            ssm[tid][q] = __expf(ssm[tid][q] - m) * inv;
    }
    __syncthreads();

    // ---- weights w[n][p] = C[n][p] + Bw[t][n][0][p]
    #pragma unroll
    for (int i = tid; i < NT * NP; i += 256)
        (&sw[0][0])[i] = (&ssm[0][0])[i] + Bw[(size_t)t * (NT * NP) + i];
    __syncthreads();

    // ---- out[n][d] = sum_p w[n][p] * U[n,p,d]   (thread o = n*16+d)
    const int n = tid >> 4;
    float acc = 0.f;
    #pragma unroll
    for (int p = 0; p < NP; p++)
        acc = fmaf(sw[n][p], su[p][tid], acc);

    // ---- squash: sq/(sq+1) * out/(norm+eps), norm over the 16 d-lanes
    float sq = acc * acc;
    #pragma unroll
    for (int off = 8; off; off >>= 1)
        sq += __shfl_xor_sync(0xffffffffu, sq, off);
    float nrm = sqrtf(sq);
    float res = (sq / (sq + 1.f)) * (acc / (nrm + 1e-7f));
    out[(size_t)bt * O_DIM + tid] = res;
}

extern "C" void kernel_launch(void* const* d_in, const int* in_sizes, int n_in,
                              void* d_out, int out_size)
{
    const float* x    = (const float*)d_in[0];   // (8,1024,32,8)
    const float* K    = (const float*)d_in[1];   // (3,8,1,256)
    const float* bias = (const float*)d_in[2];   // (256,)
    const float* Bw   = (const float*)d_in[3];   // (1024,16,1,32)
    float* out = (float*)d_out;                  // (8,1024,16,16)

    const int B  = in_sizes[0] / (T_DIM * NP * DP);   // 8
    caps_kernel<<<B * T_DIM, 256>>>(x, K, bias, Bw, out);
}

// round 3
// speedup vs baseline: 1.3466x; 1.3466x over previous
#include <cuda_runtime.h>
#include <math.h>

#define T_DIM 1024
#define NP    32
#define DP    8
#define NT    16
#define DT    16
#define O_DIM 256   // NT*DT
#define KTAP  3
#define SU_STRIDE 257   // pad to kill 32-way bank conflicts in score phase

// ---- packed f32x2 helpers (sm_10x FFMA2) ----
__device__ __forceinline__ unsigned long long pack2(float a, float b) {
    unsigned long long r;
    asm("mov.b64 %0, {%1, %2};" : "=l"(r) : "f"(a), "f"(b));
    return r;
}
__device__ __forceinline__ void unpack2(unsigned long long v, float& a, float& b) {
    asm("mov.b64 {%0, %1}, %2;" : "=f"(a), "=f"(b) : "l"(v));
}
__device__ __forceinline__ void ffma2(unsigned long long& d,
                                      unsigned long long a,
                                      unsigned long long b) {
    // d = a * b + d  (two packed fp32 lanes)
    asm("fma.rn.f32x2 %0, %1, %2, %0;" : "+l"(d) : "l"(a), "l"(b));
}

__global__ __launch_bounds__(256, 2)
void caps_kernel(const float* __restrict__ x,
                 const float* __restrict__ K,
                 const float* __restrict__ bias,
                 const float* __restrict__ Bw,
                 float* __restrict__ out)
{
    const int bt  = blockIdx.x;            // b*T + t
    const int t   = bt & (T_DIM - 1);
    const int tid = threadIdx.x;           // output channel o = n*16+d

    __shared__ float xwt[KTAP][DP][NP];        // conv window TRANSPOSED: [r][d][p], 3 KB
    __shared__ float su[NP * SU_STRIDE];       // U tile, padded rows: su[p*257 + o]
    __shared__ float sv[O_DIM];                // v[n][d] = sum_p U[n,p,d]
    __shared__ float ssm[NT][NP];              // scores -> softmax
    __shared__ float sw[NT][NP];               // C + B_weight

    // ---- load x window transposed (rows t-1,t,t+1; zero-pad at seq edges)
    {
        const int p = tid >> 3, d = tid & 7;
        const float* xbase = x + (size_t)bt * (NP * DP);
        #pragma unroll
        for (int r = 0; r < KTAP; r++) {
            int tt = t + r - 1;
            float v = 0.f;
            if (tt >= 0 && tt < T_DIM) v = xbase[(r - 1) * (NP * DP) + tid];
            xwt[r][d][p] = v;
        }
    }

    // ---- conv weights packed {k,k} for this output channel (coalesced LDG)
    unsigned long long kr2[24];
    #pragma unroll
    for (int i = 0; i < 24; i++) {
        float k = K[i * O_DIM + tid];
        kr2[i] = pack2(k, k);
    }
    const float bo = bias[tid];
    __syncthreads();

    // ---- conv + relu, 4 p's per group via FFMA2; accumulate v in-register
    float vsum = 0.f;
    #pragma unroll
    for (int g = 0; g < NP / 4; g++) {
        unsigned long long accLo = pack2(bo, bo);   // p = 4g, 4g+1
        unsigned long long accHi = accLo;           // p = 4g+2, 4g+3
        #pragma unroll
        for (int r = 0; r < KTAP; r++) {
            #pragma unroll
            for (int d = 0; d < DP; d++) {
                ulonglong2 xx = *(const ulonglong2*)&xwt[r][d][g * 4]; // LDS.128 broadcast
                ffma2(accLo, xx.x, kr2[r * 8 + d]);
                ffma2(accHi, xx.y, kr2[r * 8 + d]);
            }
        }
        float u0, u1, u2, u3;
        unpack2(accLo, u0, u1);
        unpack2(accHi, u2, u3);
        u0 = fmaxf(u0, 0.f); u1 = fmaxf(u1, 0.f);
        u2 = fmaxf(u2, 0.f); u3 = fmaxf(u3, 0.f);
        su[(g * 4 + 0) * SU_STRIDE + tid] = u0;
        su[(g * 4 + 1) * SU_STRIDE + tid] = u1;
        su[(g * 4 + 2) * SU_STRIDE + tid] = u2;
        su[(g * 4 + 3) * SU_STRIDE + tid] = u3;
        vsum += (u0 + u1) + (u2 + u3);
    }
    sv[tid] = vsum;
    __syncthreads();

    // ---- s[n][q] = dot(v[n,:], U[n,q,:]) / sqrt(8); padded stride = conflict-free
    #pragma unroll
    for (int it = 0; it < 2; it++) {
        const int i = tid + it * 256;
        const int n = i >> 5;
        const int q = i & 31;
        const float* svp = &sv[n * 16];
        const float* sup = &su[q * SU_STRIDE + n * 16];
        float acc = 0.f;
        #pragma unroll
        for (int d = 0; d < DT; d++)
            acc = fmaf(svp[d], sup[d], acc);
        ssm[n][q] = acc * 0.35355339059327373f;   // 1/sqrt(8)
    }
    __syncthreads();

    // ---- softmax over q per row n (16 rows; one thread per row)
    if (tid < NT) {
        float m = -1e30f;
        #pragma unroll
        for (int q = 0; q < NP; q++) m = fmaxf(m, ssm[tid][q]);
        float sum = 0.f;
        #pragma unroll
        for (int q = 0; q < NP; q++) {
            float e = __expf(ssm[tid][q] - m);
            ssm[tid][q] = e;
            sum += e;
        }
        float inv = 1.f / sum;
        #pragma unroll
        for (int q = 0; q < NP; q++) ssm[tid][q] *= inv;
    }
    __syncthreads();

    // ---- weights w[n][p] = C[n][p] + Bw[t][n][0][p]  (coalesced LDG)
    #pragma unroll
    for (int i = tid; i < NT * NP; i += 256)
        (&sw[0][0])[i] = (&ssm[0][0])[i] + Bw[(size_t)t * (NT * NP) + i];
    __syncthreads();

    // ---- out[n][d] = sum_p w[n][p] * U[n,p,d]
    const int n = tid >> 4;
    float acc = 0.f;
    #pragma unroll
    for (int p = 0; p < NP; p++)
        acc = fmaf(sw[n][p], su[p * SU_STRIDE + tid], acc);

    // ---- squash over the 16 d-lanes
    float sq = acc * acc;
    #pragma unroll
    for (int off = 8; off; off >>= 1)
        sq += __shfl_xor_sync(0xffffffffu, sq, off);
    float nrm = sqrtf(sq);
    float res = (sq / (sq + 1.f)) * (acc / (nrm + 1e-7f));
    out[(size_t)bt * O_DIM + tid] = res;
}

extern "C" void kernel_launch(void* const* d_in, const int* in_sizes, int n_in,
                              void* d_out, int out_size)
{
    const float* x    = (const float*)d_in[0];   // (8,1024,32,8)
    const float* K    = (const float*)d_in[1];   // (3,8,1,256)
    const float* bias = (const float*)d_in[2];   // (256,)
    const float* Bw   = (const float*)d_in[3];   // (1024,16,1,32)
    float* out = (float*)d_out;                  // (8,1024,16,16)

    const int B = in_sizes[0] / (T_DIM * NP * DP);   // 8
    caps_kernel<<<B * T_DIM, 256>>>(x, K, bias, Bw, out);
}

// round 6
// speedup vs baseline: 1.7847x; 1.3254x over previous
#include <cuda_runtime.h>
#include <math.h>

#define T_DIM 1024
#define NP    32
#define DP    8
#define NT    16
#define DT    16
#define O_DIM 256   // NT*DT
#define KTAP  3

// ---- packed f32x2 helpers (sm_10x FFMA2) ----
__device__ __forceinline__ unsigned long long pack2(float a, float b) {
    unsigned long long r;
    asm("mov.b64 %0, {%1, %2};" : "=l"(r) : "f"(a), "f"(b));
    return r;
}
__device__ __forceinline__ void unpack2(unsigned long long v, float& a, float& b) {
    asm("mov.b64 {%0, %1}, %2;" : "=f"(a), "=f"(b) : "l"(v));
}
__device__ __forceinline__ void ffma2(unsigned long long& d,
                                      unsigned long long a,
                                      unsigned long long b) {
    asm("fma.rn.f32x2 %0, %1, %2, %0;" : "+l"(d) : "l"(a), "l"(b));
}

__global__ __launch_bounds__(256, 2)
void caps_kernel(const float* __restrict__ x,
                 const float* __restrict__ K,
                 const float* __restrict__ bias,
                 const float* __restrict__ Bw,
                 float* __restrict__ out)
{
    const int bt  = blockIdx.x;            // b*T + t
    const int t   = bt & (T_DIM - 1);
    const int tid = threadIdx.x;
    const int pg  = tid & 7;               // p-group: p = pg*4 .. pg*4+3
    const int og  = tid >> 3;              // o-group: o = og*8 .. og*8+7
    const int n   = og >> 1;               // capsule index (o = n*16 + d)

    __shared__ float xwt[KTAP][DP][NP];    // conv window transposed [r][d][p], 3 KB

    // ---- stage x window (rows t-1,t,t+1; zero-pad at seq edges)
    {
        const float* xbase = x + (size_t)bt * (NP * DP);
        #pragma unroll
        for (int r = 0; r < KTAP; r++) {
            int tt = t + r - 1;
            float v = 0.f;
            if (tt >= 0 && tt < T_DIM) v = xbase[(r - 1) * (NP * DP) + tid];
            xwt[r][tid & 7][tid >> 3] = v;
        }
    }

    // ---- accumulators: U[4p][8o] as 16 f32x2 pairs, init with bias[o]
    unsigned long long acc[4][4];
    {
        float4 b0 = *(const float4*)(bias + og * 8);
        float4 b1 = *(const float4*)(bias + og * 8 + 4);
        unsigned long long p0 = pack2(b0.x, b0.y);
        unsigned long long p1 = pack2(b0.z, b0.w);
        unsigned long long p2 = pack2(b1.x, b1.y);
        unsigned long long p3 = pack2(b1.z, b1.w);
        #pragma unroll
        for (int pi = 0; pi < 4; pi++) {
            acc[pi][0] = p0; acc[pi][1] = p1; acc[pi][2] = p2; acc[pi][3] = p3;
        }
    }
    __syncthreads();

    // ---- conv: per (r,d): 1 broadcast LDS.128 (4 p's) + 2 LDG.128 (8 k's, L1-hit)
    #pragma unroll
    for (int r = 0; r < KTAP; r++) {
        #pragma unroll
        for (int d = 0; d < DP; d++) {
            float4 x4 = *(const float4*)&xwt[r][d][pg * 4];
            const float* kp = K + (r * 8 + d) * O_DIM + og * 8;
            ulonglong2 ka = *(const ulonglong2*)(kp);      // k-pairs (0,1),(2,3)
            ulonglong2 kb = *(const ulonglong2*)(kp + 4);  // k-pairs (4,5),(6,7)
            unsigned long long xx;
            xx = pack2(x4.x, x4.x);
            ffma2(acc[0][0], xx, ka.x); ffma2(acc[0][1], xx, ka.y);
            ffma2(acc[0][2], xx, kb.x); ffma2(acc[0][3], xx, kb.y);
            xx = pack2(x4.y, x4.y);
            ffma2(acc[1][0], xx, ka.x); ffma2(acc[1][1], xx, ka.y);
            ffma2(acc[1][2], xx, kb.x); ffma2(acc[1][3], xx, kb.y);
            xx = pack2(x4.z, x4.z);
            ffma2(acc[2][0], xx, ka.x); ffma2(acc[2][1], xx, ka.y);
            ffma2(acc[2][2], xx, kb.x); ffma2(acc[2][3], xx, kb.y);
            xx = pack2(x4.w, x4.w);
            ffma2(acc[3][0], xx, ka.x); ffma2(acc[3][1], xx, ka.y);
            ffma2(acc[3][2], xx, kb.x); ffma2(acc[3][3], xx, kb.y);
        }
    }

    // ---- relu, unpack to u[pi][j]; local v partial over this thread's 4 p
    float u[4][8];
    float vloc[8];
    #pragma unroll
    for (int j = 0; j < 8; j++) vloc[j] = 0.f;
    #pragma unroll
    for (int pi = 0; pi < 4; pi++) {
        #pragma unroll
        for (int jp = 0; jp < 4; jp++) {
            float a, b;
            unpack2(acc[pi][jp], a, b);
            a = fmaxf(a, 0.f); b = fmaxf(b, 0.f);
            u[pi][2 * jp]     = a;
            u[pi][2 * jp + 1] = b;
            vloc[2 * jp]     += a;
            vloc[2 * jp + 1] += b;
        }
    }

    // ---- v[n][d] over all 32 p: butterfly across the 8 pg lanes
    #pragma unroll
    for (int k = 1; k <= 4; k <<= 1) {
        #pragma unroll
        for (int j = 0; j < 8; j++)
            vloc[j] += __shfl_xor_sync(0xffffffffu, vloc[j], k);
    }

    // ---- scores s[n][q] for this thread's 4 q; og-twin (xor 8) holds other 8 d's
    float s[4];
    #pragma unroll
    for (int qi = 0; qi < 4; qi++) {
        float a = 0.f;
        #pragma unroll
        for (int j = 0; j < 8; j++) a = fmaf(vloc[j], u[qi][j], a);
        a += __shfl_xor_sync(0xffffffffu, a, 8);
        s[qi] = a * 0.35355339059327373f;   // 1/sqrt(8)
    }

    // ---- softmax over the 32 q (4 local x 8 pg lanes; og twins duplicate)
    float m = fmaxf(fmaxf(s[0], s[1]), fmaxf(s[2], s[3]));
    #pragma unroll
    for (int k = 1; k <= 4; k <<= 1)
        m = fmaxf(m, __shfl_xor_sync(0xffffffffu, m, k));
    float e[4];
    float sum = 0.f;
    #pragma unroll
    for (int qi = 0; qi < 4; qi++) { e[qi] = __expf(s[qi] - m); sum += e[qi]; }
    #pragma unroll
    for (int k = 1; k <= 4; k <<= 1)
        sum += __shfl_xor_sync(0xffffffffu, sum, k);
    const float inv = 1.f / sum;

    // ---- mixing weights w[q] = C[n][q] + Bw[t][n][q] (coalesced LDG.128)
    float4 bw = *(const float4*)(Bw + (size_t)t * (NT * NP) + n * NP + pg * 4);
    float w0 = fmaf(e[0], inv, bw.x);
    float w1 = fmaf(e[1], inv, bw.y);
    float w2 = fmaf(e[2], inv, bw.z);
    float w3 = fmaf(e[3], inv, bw.w);

    // ---- out partials over local 4 q, then reduce-scatter over the 8 pg lanes
    float po[8];
    #pragma unroll
    for (int j = 0; j < 8; j++) {
        float a = w0 * u[0][j];
        a = fmaf(w1, u[1][j], a);
        a = fmaf(w2, u[2][j], a);
        a = fmaf(w3, u[3][j], a);
        po[j] = a;
    }
    #pragma unroll
    for (int k = 4; k >= 1; k >>= 1) {
        const int sel = pg & k;
        #pragma unroll
        for (int j = 0; j < k; j++) {
            float a = po[j], b = po[j + k];
            float snd = sel ? a : b;
            float rcv = __shfl_xor_sync(0xffffffffu, snd, k);
            po[j] = (sel ? b : a) + rcv;
        }
    }
    const float o_val = po[0];   // fully-summed out[n][d] for o = og*8+pg = tid

    // ---- squash over the 16 d-lanes of capsule n (lanes tid>>4 group)
    float sq = o_val * o_val;
    #pragma unroll
    for (int off = 1; off <= 8; off <<= 1)
        sq += __shfl_xor_sync(0xffffffffu, sq, off);
    float nrm = sqrtf(sq);
    out[(size_t)bt * O_DIM + tid] = (sq / (sq + 1.f)) * (o_val / (nrm + 1e-7f));
}

extern "C" void kernel_launch(void* const* d_in, const int* in_sizes, int n_in,
                              void* d_out, int out_size)
{
    const float* x    = (const float*)d_in[0];   // (8,1024,32,8)
    const float* K    = (const float*)d_in[1];   // (3,8,1,256)
    const float* bias = (const float*)d_in[2];   // (256,)
    const float* Bw   = (const float*)d_in[3];   // (1024,16,1,32)
    float* out = (float*)d_out;                  // (8,1024,16,16)

    const int B = in_sizes[0] / (T_DIM * NP * DP);   // 8
    caps_kernel<<<B * T_DIM, 256>>>(x, K, bias, Bw, out);
}